// round 10
// baseline (speedup 1.0000x reference)
#include <cuda_runtime.h>
#include <cuda_bf16.h>
#include <cuda_fp16.h>
#include <cstdint>

#define NN 50000
#define DEG 16

#define TSTRIDE 136
#define BT_HALVES (128 * TSTRIDE)        // B tile: 17408 halves = 34816 B
#define AT_BYTES  (64 * TSTRIDE * 2)     // A tile (64 rows): 17408 B
#define BT_BYTES  (BT_HALVES * 2)        // 34816 B
#define SM_TOTAL  (2 * AT_BYTES + 2 * BT_BYTES)  // 104448 B

// Scratch
__device__ float g_A[(size_t)NN * 128];    // x @ Wm_top (fp32)
__device__ uint4 g_bx[(size_t)NN * 32];    // packed per node: [B fp16 x4 | x fp16 x4]
__device__ uint2 g_xnh[(size_t)NN * 32];   // x_new fp16
__device__ float g_g[(size_t)NN * 128];    // segment_sum(adj * x_new[src])
// Pre-converted weights: [matrix 0=Wm_top,1=Wm_bot,2=weight][hi,lo][padded tile]
__device__ __nv_bfloat16 g_wt[3][2][BT_HALVES];

// ───────────────── tensor-core helpers (sm_80 baseline PTX) ─────────────────
__device__ __forceinline__ uint32_t smem_u32(const void* p) {
    uint32_t a;
    asm("{ .reg .u64 t; cvta.to.shared.u64 t, %1; cvt.u32.u64 %0, t; }"
        : "=r"(a) : "l"(p));
    return a;
}
__device__ __forceinline__ void ldsm_x4(uint32_t& r0, uint32_t& r1,
                                        uint32_t& r2, uint32_t& r3,
                                        uint32_t addr) {
    asm volatile("ldmatrix.sync.aligned.m8n8.x4.shared.b16 {%0,%1,%2,%3}, [%4];"
                 : "=r"(r0), "=r"(r1), "=r"(r2), "=r"(r3) : "r"(addr));
}
__device__ __forceinline__ void mma_bf16(float* c, const uint32_t* a,
                                         const uint32_t* b) {
    asm volatile(
        "mma.sync.aligned.m16n8k16.row.col.f32.bf16.bf16.f32 "
        "{%0,%1,%2,%3}, {%4,%5,%6,%7}, {%8,%9}, {%0,%1,%2,%3};"
        : "+f"(c[0]), "+f"(c[1]), "+f"(c[2]), "+f"(c[3])
        : "r"(a[0]), "r"(a[1]), "r"(a[2]), "r"(a[3]), "r"(b[0]), "r"(b[1]));
}

__device__ __forceinline__ void cvt_pair(float v, __nv_bfloat16& h, __nv_bfloat16& l) {
    h = __float2bfloat16_rn(v);
    l = __float2bfloat16_rn(v - (float)h);
}

// ---------------------------------------------------------------------------
// One-time weight conversion: W[k][n] fp32 -> B-tile images B[n][k] bf16 hi/lo
// in the padded (TSTRIDE) smem layout, so GEMM CTAs do a raw vector copy.
// grid (3): 0=Wm_top, 1=Wm_bot, 2=weight
// ---------------------------------------------------------------------------
__global__ __launch_bounds__(256) void wconv_k(
    const float* __restrict__ wm, const float* __restrict__ weight)
{
    const int m = blockIdx.x;
    const float* src = (m == 0) ? wm : (m == 1) ? wm + 128 * 128 : weight;
    for (int idx = threadIdx.x; idx < 128 * 128; idx += 256) {
        const int k = idx >> 7, n = idx & 127;
        const float v = src[k * 128 + n];
        __nv_bfloat16 h, l;
        cvt_pair(v, h, l);
        g_wt[m][0][n * TSTRIDE + k] = h;
        g_wt[m][1][n * TSTRIDE + k] = l;
    }
}

// ===========================================================================
// GEMM core: 64(M) x 128(N) x 128(K) tile, 3-pass bf16 split, 8 warps,
// warp tile 32x32. B tiles copied raw from pre-converted gmem images.
// ===========================================================================
struct GemmCtx {
    float acc[2][4][4];
    int mr, nc;
};

__device__ __forceinline__ void gemm_core(
    char* sh, const float* __restrict__ X, const __nv_bfloat16* __restrict__ wt,
    int row0, int M, GemmCtx& g, bool pack_x)
{
    __nv_bfloat16* Ahi = (__nv_bfloat16*)(sh);
    __nv_bfloat16* Alo = (__nv_bfloat16*)(sh + AT_BYTES);

    const int tid  = threadIdx.x;
    const int lane = tid & 31;
    const int wid  = tid >> 5;

    // ---- A: load + split-convert 64 rows (thread t: row t>>2, k-quarter t&3)
    {
        const int r  = tid >> 2;
        const int kq = (tid & 3) * 32;
        const bool valid = (row0 + r) < M;
        const float4* Xr = (const float4*)(X + (size_t)(row0 + r) * 128 + kq);
#pragma unroll 8
        for (int kk = 0; kk < 32; kk += 4) {
            float4 v = valid ? Xr[kk >> 2] : make_float4(0.f, 0.f, 0.f, 0.f);
            __nv_bfloat16 h0, l0, h1, l1, h2, l2, h3, l3;
            cvt_pair(v.x, h0, l0); cvt_pair(v.y, h1, l1);
            cvt_pair(v.z, h2, l2); cvt_pair(v.w, h3, l3);
            __nv_bfloat162 hA = {h0, h1}, hB = {h2, h3};
            __nv_bfloat162 lA = {l0, l1}, lB = {l2, l3};
            const int k = kq + kk;
            *(uint2*)&Ahi[r * TSTRIDE + k] = make_uint2(*(uint32_t*)&hA, *(uint32_t*)&hB);
            *(uint2*)&Alo[r * TSTRIDE + k] = make_uint2(*(uint32_t*)&lA, *(uint32_t*)&lB);
            if (pack_x && valid) {
                __half2 x01 = __floats2half2_rn(v.x, v.y);
                __half2 x23 = __floats2half2_rn(v.z, v.w);
                *(uint2*)((char*)&g_bx[(size_t)(row0 + r) * 32 + (k >> 2)] + 8) =
                    make_uint2(*(uint32_t*)&x01, *(uint32_t*)&x23);
            }
        }
    }
    // ---- B: raw copy hi+lo tile images (2*34816 B = 4352 uint4, coalesced)
    {
        const uint4* src = (const uint4*)wt;
        uint4* dst = (uint4*)(sh + 2 * AT_BYTES);
#pragma unroll
        for (int i = 0; i < 17; i++)
            dst[tid + i * 256] = src[tid + i * 256];
    }
    __syncthreads();

    g.mr = (wid & 1) * 32;
    g.nc = (wid >> 1) * 32;
#pragma unroll
    for (int tm = 0; tm < 2; tm++)
#pragma unroll
        for (int j = 0; j < 4; j++)
#pragma unroll
            for (int q = 0; q < 4; q++) g.acc[tm][j][q] = 0.f;

    const uint32_t sb = smem_u32(sh);
    const uint32_t a_lane = ((lane & 15) * TSTRIDE + (lane >> 4) * 8) * 2;
    const uint32_t sA[2] = { sb + (uint32_t)(g.mr * TSTRIDE * 2) + a_lane,
                             sb + (uint32_t)((g.mr + 16) * TSTRIDE * 2) + a_lane };
    const uint32_t bbase = sb + 2 * AT_BYTES;
    const uint32_t sB[2] = { bbase + (uint32_t)(g.nc * TSTRIDE * 2) + a_lane,
                             bbase + (uint32_t)((g.nc + 16) * TSTRIDE * 2) + a_lane };

    const uint32_t aoff[3] = { 0u, 0u, (uint32_t)AT_BYTES };
    const uint32_t boff[3] = { 0u, (uint32_t)BT_BYTES, 0u };

#pragma unroll 1
    for (int p = 0; p < 3; p++) {
#pragma unroll
        for (int kk = 0; kk < 8; kk++) {
            const uint32_t kb = kk * 32;
            uint32_t a[2][4];
            ldsm_x4(a[0][0], a[0][1], a[0][2], a[0][3], sA[0] + aoff[p] + kb);
            ldsm_x4(a[1][0], a[1][1], a[1][2], a[1][3], sA[1] + aoff[p] + kb);
            uint32_t b[4][2];
#pragma unroll
            for (int jp = 0; jp < 2; jp++) {
                uint32_t m0, m1, m2, m3;
                ldsm_x4(m0, m1, m2, m3, sB[jp] + boff[p] + kb);
                b[2 * jp][0] = m0; b[2 * jp][1] = m2;
                b[2 * jp + 1][0] = m1; b[2 * jp + 1][1] = m3;
            }
#pragma unroll
            for (int tm = 0; tm < 2; tm++)
#pragma unroll
                for (int j = 0; j < 4; j++)
                    mma_bf16(g.acc[tm][j], a[tm], b[j]);
        }
    }
}

// ---------------------------------------------------------------------------
// Fused Wm GEMM: grid (tiles, 2). y=0: A = x@Wm_top -> g_A fp32 (+ pack x fp16)
//                                y=1: B = x@Wm_bot -> packed fp16 in g_bx
// ---------------------------------------------------------------------------
__global__ __launch_bounds__(256, 2) void wm_gemm_k(
    const float* __restrict__ X, int M)
{
    extern __shared__ char sh[];
    const int row0 = blockIdx.x * 64;
    const int half = blockIdx.y;
    GemmCtx g;
    gemm_core(sh, X, g_wt[half][0], row0, M, g, half == 0);

    const int lane = threadIdx.x & 31;
#pragma unroll
    for (int j = 0; j < 4; j++) {
        const int col = g.nc + j * 8 + (lane & 3) * 2;
#pragma unroll
        for (int tm = 0; tm < 2; tm++) {
            const int ra = row0 + g.mr + tm * 16 + (lane >> 2);
            const int rb = ra + 8;
            if (half == 0) {
                if (ra < M)
                    *(float2*)(g_A + (size_t)ra * 128 + col) =
                        make_float2(g.acc[tm][j][0], g.acc[tm][j][1]);
                if (rb < M)
                    *(float2*)(g_A + (size_t)rb * 128 + col) =
                        make_float2(g.acc[tm][j][2], g.acc[tm][j][3]);
            } else {
                const uint32_t off = (uint32_t)((col >> 2) * 16 + (col & 3) * 2);
                if (ra < M) {
                    __half2 h = __floats2half2_rn(g.acc[tm][j][0], g.acc[tm][j][1]);
                    *(uint32_t*)((char*)&g_bx[(size_t)ra * 32] + off) = *(uint32_t*)&h;
                }
                if (rb < M) {
                    __half2 h = __floats2half2_rn(g.acc[tm][j][2], g.acc[tm][j][3]);
                    *(uint32_t*)((char*)&g_bx[(size_t)rb * 32] + off) = *(uint32_t*)&h;
                }
            }
        }
    }
}

// ---------------------------------------------------------------------------
// Final GEMM: out = g_g @ weight + bias
// ---------------------------------------------------------------------------
__global__ __launch_bounds__(256, 2) void tc_gemm_k(
    const float* __restrict__ X, const float* __restrict__ bias,
    float* __restrict__ C, int M)
{
    extern __shared__ char sh[];
    const int row0 = blockIdx.x * 64;
    GemmCtx g;
    gemm_core(sh, X, g_wt[2][0], row0, M, g, false);

    const int lane = threadIdx.x & 31;
#pragma unroll
    for (int j = 0; j < 4; j++) {
        const int col = g.nc + j * 8 + (lane & 3) * 2;
        const float2 bv = *(const float2*)(bias + col);
#pragma unroll
        for (int tm = 0; tm < 2; tm++) {
            const int ra = row0 + g.mr + tm * 16 + (lane >> 2);
            const int rb = ra + 8;
            if (ra < M)
                *(float2*)(C + (size_t)ra * 128 + col) =
                    make_float2(g.acc[tm][j][0] + bv.x, g.acc[tm][j][1] + bv.y);
            if (rb < M)
                *(float2*)(C + (size_t)rb * 128 + col) =
                    make_float2(g.acc[tm][j][2] + bv.x, g.acc[tm][j][3] + bv.y);
        }
    }
}

__device__ __forceinline__ float sig_t(float half_arg) {
    // sigmoid(2*half_arg) = 0.5*tanh(half_arg) + 0.5
    float t;
    asm("tanh.approx.f32 %0, %1;" : "=f"(t) : "f"(half_arg));
    return fmaf(0.5f, t, 0.5f);
}

// ---------------------------------------------------------------------------
// Warp per node: x_new[c] = x[c] + sum_e sigmoid(A[c]+B[s]) * x[s]
// One LDG.128 per lane per edge from the packed [B fp16|x fp16] record.
// ---------------------------------------------------------------------------
__global__ __launch_bounds__(256) void edge_agg_k(
    const float* __restrict__ x, const int* __restrict__ esrc)
{
    const int gw   = (blockIdx.x * 256 + threadIdx.x) >> 5;
    const int lane = threadIdx.x & 31;
    if (gw >= NN) return;
    const int c    = gw;
    const int s_my = esrc[c * DEG + (lane & 15)];

    const float4 a = ((const float4*)g_A)[(size_t)c * 32 + lane];
    const __half2 h05  = __floats2half2_rn(0.5f, 0.5f);
    const __half2 ha01 = __floats2half2_rn(0.5f * a.x, 0.5f * a.y);
    const __half2 ha23 = __floats2half2_rn(0.5f * a.z, 0.5f * a.w);

    float4 acc = make_float4(0.f, 0.f, 0.f, 0.f);

#pragma unroll
    for (int e = 0; e < DEG; e++) {
        const int   s = __shfl_sync(0xffffffffu, s_my, e);
        const uint4 p = g_bx[(size_t)s * 32 + lane];
        const __half2 b01 = *(const __half2*)&p.x;
        const __half2 b23 = *(const __half2*)&p.y;
        const float2 h01 = __half22float2(__hfma2(b01, h05, ha01));
        const float2 h23 = __half22float2(__hfma2(b23, h05, ha23));
        const float2 xf01 = __half22float2(*(const __half2*)&p.z);
        const float2 xf23 = __half22float2(*(const __half2*)&p.w);
        acc.x = fmaf(sig_t(h01.x), xf01.x, acc.x);
        acc.y = fmaf(sig_t(h01.y), xf01.y, acc.y);
        acc.z = fmaf(sig_t(h23.x), xf23.x, acc.z);
        acc.w = fmaf(sig_t(h23.y), xf23.y, acc.w);
    }

    const float4 xc = ((const float4*)x)[(size_t)c * 32 + lane];
    __half2 o01 = __floats2half2_rn(xc.x + acc.x, xc.y + acc.y);
    __half2 o23 = __floats2half2_rn(xc.z + acc.z, xc.w + acc.w);
    g_xnh[(size_t)c * 32 + lane] = make_uint2(*(uint32_t*)&o01, *(uint32_t*)&o23);
}

// ---------------------------------------------------------------------------
// Warp per node: g[c] = sum_e adj[e] * x_new_fp16[s_e]  (fp32 out)
// ---------------------------------------------------------------------------
__global__ __launch_bounds__(256) void gather_k(
    const float* __restrict__ adj, const int* __restrict__ esrc)
{
    const int gw   = (blockIdx.x * 256 + threadIdx.x) >> 5;
    const int lane = threadIdx.x & 31;
    if (gw >= NN) return;
    const int   c    = gw;
    const int   s_my = esrc[c * DEG + (lane & 15)];
    const float a_my = adj[c * DEG + (lane & 15)];

    float4 acc = make_float4(0.f, 0.f, 0.f, 0.f);

#pragma unroll
    for (int e = 0; e < DEG; e++) {
        const int   s  = __shfl_sync(0xffffffffu, s_my, e);
        const float av = __shfl_sync(0xffffffffu, a_my, e);
        const uint2 p  = g_xnh[(size_t)s * 32 + lane];
        const float2 v01 = __half22float2(*(const __half2*)&p.x);
        const float2 v23 = __half22float2(*(const __half2*)&p.y);
        acc.x = fmaf(av, v01.x, acc.x);
        acc.y = fmaf(av, v01.y, acc.y);
        acc.z = fmaf(av, v23.x, acc.z);
        acc.w = fmaf(av, v23.y, acc.w);
    }
    ((float4*)g_g)[(size_t)c * 32 + lane] = acc;
}

// ---------------------------------------------------------------------------
extern "C" void kernel_launch(void* const* d_in, const int* in_sizes, int n_in,
                              void* d_out, int out_size)
{
    const float* x      = (const float*)d_in[0];  // [N,128]
    const float* weight = (const float*)d_in[1];  // [128,128]
    const float* bias   = (const float*)d_in[2];  // [128]
    const float* wm     = (const float*)d_in[3];  // [256,128]
    const float* adj    = (const float*)d_in[4];  // [E]
    const int*   esrc   = (const int*)d_in[5];    // [E]
    float* out = (float*)d_out;

    void* pg;
    cudaGetSymbolAddress(&pg, g_g);

    cudaFuncSetAttribute(wm_gemm_k, cudaFuncAttributeMaxDynamicSharedMemorySize,
                         SM_TOTAL);
    cudaFuncSetAttribute(tc_gemm_k, cudaFuncAttributeMaxDynamicSharedMemorySize,
                         SM_TOTAL);

    const int gemm_grid = (NN + 63) / 64;   // 782
    const int warp_grid = (NN + 7) / 8;     // 6250

    // One-time weight conversion (3 matrices -> padded bf16 hi/lo images)
    wconv_k<<<3, 256>>>(wm, weight);

    // A = x@Wm_top (fp32) ; packed [B fp16 | x fp16] record
    wm_gemm_k<<<dim3(gemm_grid, 2), 256, SM_TOTAL>>>(x, NN);

    // x_new (fp16) = x + sum_e sigmoid(A[c]+B[s]) * x[s]
    edge_agg_k<<<warp_grid, 256>>>(x, esrc);

    // g[c] = sum_e adj[e] * x_new[s]
    gather_k<<<warp_grid, 256>>>(adj, esrc);

    // out = g @ weight + bias
    tc_gemm_k<<<gemm_grid, 256, SM_TOTAL>>>((const float*)pg, bias, out, NN);
}

// round 11
// speedup vs baseline: 1.0156x; 1.0156x over previous
#include <cuda_runtime.h>
#include <cuda_bf16.h>
#include <cuda_fp16.h>
#include <cstdint>

#define NN 50000
#define DEG 16

#define TSTRIDE 136
#define AT_BYTES  (128 * TSTRIDE * 2)    // one A tile (128 rows) = 34816 B
#define BT_HALVES (128 * TSTRIDE)
#define BT_BYTES  (BT_HALVES * 2)        // one B tile = 34816 B
#define SM_TOTAL  (2 * AT_BYTES + BT_BYTES)  // Ahi|Alo|Bbuf = 104448 B

// Scratch
__device__ float g_A[(size_t)NN * 128];    // x @ Wm_top (fp32)
__device__ uint4 g_bx[(size_t)NN * 32];    // packed per node: [B fp16 x4 | x fp16 x4]
__device__ uint2 g_xnh[(size_t)NN * 32];   // x_new fp16
__device__ float g_g[(size_t)NN * 128];    // segment_sum(adj * x_new[src])
// Pre-converted weights: [matrix 0=Wm_top,1=Wm_bot,2=weight][hi,lo][padded tile]
__device__ __nv_bfloat16 g_wt[3][2][BT_HALVES];

// ───────────────── tensor-core helpers (sm_80 baseline PTX) ─────────────────
__device__ __forceinline__ uint32_t smem_u32(const void* p) {
    uint32_t a;
    asm("{ .reg .u64 t; cvta.to.shared.u64 t, %1; cvt.u32.u64 %0, t; }"
        : "=r"(a) : "l"(p));
    return a;
}
__device__ __forceinline__ void ldsm_x4(uint32_t& r0, uint32_t& r1,
                                        uint32_t& r2, uint32_t& r3,
                                        uint32_t addr) {
    asm volatile("ldmatrix.sync.aligned.m8n8.x4.shared.b16 {%0,%1,%2,%3}, [%4];"
                 : "=r"(r0), "=r"(r1), "=r"(r2), "=r"(r3) : "r"(addr));
}
__device__ __forceinline__ void mma_bf16(float* c, const uint32_t* a,
                                         const uint32_t* b) {
    asm volatile(
        "mma.sync.aligned.m16n8k16.row.col.f32.bf16.bf16.f32 "
        "{%0,%1,%2,%3}, {%4,%5,%6,%7}, {%8,%9}, {%0,%1,%2,%3};"
        : "+f"(c[0]), "+f"(c[1]), "+f"(c[2]), "+f"(c[3])
        : "r"(a[0]), "r"(a[1]), "r"(a[2]), "r"(a[3]), "r"(b[0]), "r"(b[1]));
}

__device__ __forceinline__ void cvt_pair(float v, __nv_bfloat16& h, __nv_bfloat16& l) {
    h = __float2bfloat16_rn(v);
    l = __float2bfloat16_rn(v - (float)h);
}

// ---------------------------------------------------------------------------
// One-time weight conversion: W[k][n] fp32 -> B-tile images B[n][k] bf16 hi/lo
// in the padded layout, so GEMM CTAs do raw vector copies.
// ---------------------------------------------------------------------------
__global__ __launch_bounds__(256) void wconv_k(
    const float* __restrict__ wm, const float* __restrict__ weight)
{
    const int m = blockIdx.x;
    const float* src = (m == 0) ? wm : (m == 1) ? wm + 128 * 128 : weight;
    for (int idx = threadIdx.x; idx < 128 * 128; idx += 256) {
        const int k = idx >> 7, n = idx & 127;
        const float v = src[k * 128 + n];
        __nv_bfloat16 h, l;
        cvt_pair(v, h, l);
        g_wt[m][0][n * TSTRIDE + k] = h;
        g_wt[m][1][n * TSTRIDE + k] = l;
    }
}

// copy one 34816-B B-tile image into the smem B buffer (coalesced uint4)
__device__ __forceinline__ void copy_btile(char* dst, const __nv_bfloat16* src) {
    const uint4* s = (const uint4*)src;
    uint4* d = (uint4*)dst;
    const int tid = threadIdx.x;
#pragma unroll
    for (int i = 0; i < 9; i++) {
        const int idx = tid + i * 256;
        if (idx < 2176) d[idx] = s[idx];
    }
}

// ===========================================================================
// GEMM core: 128x128x128 tile, 3-pass bf16 split with single resident B
// buffer (pass order Ahi*Bhi, Alo*Bhi, Ahi*Blo). 8 warps, warp tile 32x64.
// 104.4 KB smem -> 2 CTAs/SM.
// ===========================================================================
struct GemmCtx {
    float acc[2][8][4];
    int mr, nc;
};

__device__ __forceinline__ void gemm_core(
    char* sh, const float* __restrict__ X, const __nv_bfloat16* __restrict__ wt_hi,
    const __nv_bfloat16* __restrict__ wt_lo, int row0, int M, GemmCtx& g,
    bool pack_x)
{
    __nv_bfloat16* Ahi = (__nv_bfloat16*)(sh);
    __nv_bfloat16* Alo = (__nv_bfloat16*)(sh + AT_BYTES);
    char* Bbuf = sh + 2 * AT_BYTES;

    const int tid  = threadIdx.x;
    const int lane = tid & 31;
    const int wid  = tid >> 5;

    // ---- A: load + split-convert 128 rows; thread t: row t>>1, k-half (t&1)*64
    {
        const int r  = tid >> 1;
        const int kh = (tid & 1) * 64;
        const bool valid = (row0 + r) < M;
        const float4* Xr = (const float4*)(X + (size_t)(row0 + r) * 128 + kh);
#pragma unroll
        for (int kk = 0; kk < 64; kk += 4) {
            float4 v = valid ? Xr[kk >> 2] : make_float4(0.f, 0.f, 0.f, 0.f);
            __nv_bfloat16 h0, l0, h1, l1, h2, l2, h3, l3;
            cvt_pair(v.x, h0, l0); cvt_pair(v.y, h1, l1);
            cvt_pair(v.z, h2, l2); cvt_pair(v.w, h3, l3);
            __nv_bfloat162 hA = {h0, h1}, hB = {h2, h3};
            __nv_bfloat162 lA = {l0, l1}, lB = {l2, l3};
            const int k = kh + kk;
            *(uint2*)&Ahi[r * TSTRIDE + k] = make_uint2(*(uint32_t*)&hA, *(uint32_t*)&hB);
            *(uint2*)&Alo[r * TSTRIDE + k] = make_uint2(*(uint32_t*)&lA, *(uint32_t*)&lB);
            if (pack_x && valid) {
                __half2 x01 = __floats2half2_rn(v.x, v.y);
                __half2 x23 = __floats2half2_rn(v.z, v.w);
                *(uint2*)((char*)&g_bx[(size_t)(row0 + r) * 32 + (k >> 2)] + 8) =
                    make_uint2(*(uint32_t*)&x01, *(uint32_t*)&x23);
            }
        }
    }
    copy_btile(Bbuf, wt_hi);
    __syncthreads();

    g.mr = (wid & 3) * 32;
    g.nc = (wid >> 2) * 64;
#pragma unroll
    for (int tm = 0; tm < 2; tm++)
#pragma unroll
        for (int j = 0; j < 8; j++)
#pragma unroll
            for (int q = 0; q < 4; q++) g.acc[tm][j][q] = 0.f;

    const uint32_t sb = smem_u32(sh);
    const uint32_t a_lane = ((lane & 15) * TSTRIDE + (lane >> 4) * 8) * 2;
    const uint32_t sA[2] = { sb + (uint32_t)(g.mr * TSTRIDE * 2) + a_lane,
                             sb + (uint32_t)((g.mr + 16) * TSTRIDE * 2) + a_lane };
    const uint32_t bbase = sb + 2 * AT_BYTES;
    const uint32_t sB[4] = { bbase + (uint32_t)(g.nc * TSTRIDE * 2) + a_lane,
                             bbase + (uint32_t)((g.nc + 16) * TSTRIDE * 2) + a_lane,
                             bbase + (uint32_t)((g.nc + 32) * TSTRIDE * 2) + a_lane,
                             bbase + (uint32_t)((g.nc + 48) * TSTRIDE * 2) + a_lane };

    // pass p: A from {Ahi, Alo, Ahi}; B buffer holds {Bhi, Bhi, Blo}
    const uint32_t aoff[3] = { 0u, (uint32_t)AT_BYTES, 0u };

#pragma unroll 1
    for (int p = 0; p < 3; p++) {
        if (p == 2) {
            __syncthreads();            // all warps done reading Bhi
            copy_btile(Bbuf, wt_lo);
            __syncthreads();
        }
#pragma unroll
        for (int kk = 0; kk < 8; kk++) {
            const uint32_t kb = kk * 32;
            uint32_t a[2][4];
            ldsm_x4(a[0][0], a[0][1], a[0][2], a[0][3], sA[0] + aoff[p] + kb);
            ldsm_x4(a[1][0], a[1][1], a[1][2], a[1][3], sA[1] + aoff[p] + kb);
            uint32_t b[8][2];
#pragma unroll
            for (int jp = 0; jp < 4; jp++) {
                uint32_t m0, m1, m2, m3;
                ldsm_x4(m0, m1, m2, m3, sB[jp] + kb);
                b[2 * jp][0] = m0; b[2 * jp][1] = m2;
                b[2 * jp + 1][0] = m1; b[2 * jp + 1][1] = m3;
            }
#pragma unroll
            for (int tm = 0; tm < 2; tm++)
#pragma unroll
                for (int j = 0; j < 8; j++)
                    mma_bf16(g.acc[tm][j], a[tm], b[j]);
        }
    }
}

// ---------------------------------------------------------------------------
// Fused Wm GEMM: grid (tiles, 2). y=0: A = x@Wm_top -> g_A fp32 (+ pack x fp16)
//                                y=1: B = x@Wm_bot -> packed fp16 in g_bx
// ---------------------------------------------------------------------------
__global__ __launch_bounds__(256, 2) void wm_gemm_k(
    const float* __restrict__ X, int M)
{
    extern __shared__ char sh[];
    const int row0 = blockIdx.x * 128;
    const int half = blockIdx.y;
    GemmCtx g;
    gemm_core(sh, X, g_wt[half][0], g_wt[half][1], row0, M, g, half == 0);

    const int lane = threadIdx.x & 31;
#pragma unroll
    for (int j = 0; j < 8; j++) {
        const int col = g.nc + j * 8 + (lane & 3) * 2;
#pragma unroll
        for (int tm = 0; tm < 2; tm++) {
            const int ra = row0 + g.mr + tm * 16 + (lane >> 2);
            const int rb = ra + 8;
            if (half == 0) {
                if (ra < M)
                    *(float2*)(g_A + (size_t)ra * 128 + col) =
                        make_float2(g.acc[tm][j][0], g.acc[tm][j][1]);
                if (rb < M)
                    *(float2*)(g_A + (size_t)rb * 128 + col) =
                        make_float2(g.acc[tm][j][2], g.acc[tm][j][3]);
            } else {
                const uint32_t off = (uint32_t)((col >> 2) * 16 + (col & 3) * 2);
                if (ra < M) {
                    __half2 h = __floats2half2_rn(g.acc[tm][j][0], g.acc[tm][j][1]);
                    *(uint32_t*)((char*)&g_bx[(size_t)ra * 32] + off) = *(uint32_t*)&h;
                }
                if (rb < M) {
                    __half2 h = __floats2half2_rn(g.acc[tm][j][2], g.acc[tm][j][3]);
                    *(uint32_t*)((char*)&g_bx[(size_t)rb * 32] + off) = *(uint32_t*)&h;
                }
            }
        }
    }
}

// ---------------------------------------------------------------------------
// Final GEMM: out = g_g @ weight + bias
// ---------------------------------------------------------------------------
__global__ __launch_bounds__(256, 2) void tc_gemm_k(
    const float* __restrict__ X, const float* __restrict__ bias,
    float* __restrict__ C, int M)
{
    extern __shared__ char sh[];
    const int row0 = blockIdx.x * 128;
    GemmCtx g;
    gemm_core(sh, X, g_wt[2][0], g_wt[2][1], row0, M, g, false);

    const int lane = threadIdx.x & 31;
#pragma unroll
    for (int j = 0; j < 8; j++) {
        const int col = g.nc + j * 8 + (lane & 3) * 2;
        const float2 bv = *(const float2*)(bias + col);
#pragma unroll
        for (int tm = 0; tm < 2; tm++) {
            const int ra = row0 + g.mr + tm * 16 + (lane >> 2);
            const int rb = ra + 8;
            if (ra < M)
                *(float2*)(C + (size_t)ra * 128 + col) =
                    make_float2(g.acc[tm][j][0] + bv.x, g.acc[tm][j][1] + bv.y);
            if (rb < M)
                *(float2*)(C + (size_t)rb * 128 + col) =
                    make_float2(g.acc[tm][j][2] + bv.x, g.acc[tm][j][3] + bv.y);
        }
    }
}

__device__ __forceinline__ float sig_t(float half_arg) {
    // sigmoid(2*half_arg) = 0.5*tanh(half_arg) + 0.5
    float t;
    asm("tanh.approx.f32 %0, %1;" : "=f"(t) : "f"(half_arg));
    return fmaf(0.5f, t, 0.5f);
}

// ---------------------------------------------------------------------------
// Warp per node: x_new[c] = x[c] + sum_e sigmoid(A[c]+B[s]) * x[s]
// ---------------------------------------------------------------------------
__global__ __launch_bounds__(256) void edge_agg_k(
    const float* __restrict__ x, const int* __restrict__ esrc)
{
    const int gw   = (blockIdx.x * 256 + threadIdx.x) >> 5;
    const int lane = threadIdx.x & 31;
    if (gw >= NN) return;
    const int c    = gw;
    const int s_my = esrc[c * DEG + (lane & 15)];

    const float4 a = ((const float4*)g_A)[(size_t)c * 32 + lane];
    const __half2 h05  = __floats2half2_rn(0.5f, 0.5f);
    const __half2 ha01 = __floats2half2_rn(0.5f * a.x, 0.5f * a.y);
    const __half2 ha23 = __floats2half2_rn(0.5f * a.z, 0.5f * a.w);

    float4 acc = make_float4(0.f, 0.f, 0.f, 0.f);

#pragma unroll
    for (int e = 0; e < DEG; e++) {
        const int   s = __shfl_sync(0xffffffffu, s_my, e);
        const uint4 p = g_bx[(size_t)s * 32 + lane];
        const __half2 b01 = *(const __half2*)&p.x;
        const __half2 b23 = *(const __half2*)&p.y;
        const float2 h01 = __half22float2(__hfma2(b01, h05, ha01));
        const float2 h23 = __half22float2(__hfma2(b23, h05, ha23));
        const float2 xf01 = __half22float2(*(const __half2*)&p.z);
        const float2 xf23 = __half22float2(*(const __half2*)&p.w);
        acc.x = fmaf(sig_t(h01.x), xf01.x, acc.x);
        acc.y = fmaf(sig_t(h01.y), xf01.y, acc.y);
        acc.z = fmaf(sig_t(h23.x), xf23.x, acc.z);
        acc.w = fmaf(sig_t(h23.y), xf23.y, acc.w);
    }

    const float4 xc = ((const float4*)x)[(size_t)c * 32 + lane];
    __half2 o01 = __floats2half2_rn(xc.x + acc.x, xc.y + acc.y);
    __half2 o23 = __floats2half2_rn(xc.z + acc.z, xc.w + acc.w);
    g_xnh[(size_t)c * 32 + lane] = make_uint2(*(uint32_t*)&o01, *(uint32_t*)&o23);
}

// ---------------------------------------------------------------------------
// Warp per node: g[c] = sum_e adj[e] * x_new_fp16[s_e]  (fp32 out)
// ---------------------------------------------------------------------------
__global__ __launch_bounds__(256) void gather_k(
    const float* __restrict__ adj, const int* __restrict__ esrc)
{
    const int gw   = (blockIdx.x * 256 + threadIdx.x) >> 5;
    const int lane = threadIdx.x & 31;
    if (gw >= NN) return;
    const int   c    = gw;
    const int   s_my = esrc[c * DEG + (lane & 15)];
    const float a_my = adj[c * DEG + (lane & 15)];

    float4 acc = make_float4(0.f, 0.f, 0.f, 0.f);

#pragma unroll
    for (int e = 0; e < DEG; e++) {
        const int   s  = __shfl_sync(0xffffffffu, s_my, e);
        const float av = __shfl_sync(0xffffffffu, a_my, e);
        const uint2 p  = g_xnh[(size_t)s * 32 + lane];
        const float2 v01 = __half22float2(*(const __half2*)&p.x);
        const float2 v23 = __half22float2(*(const __half2*)&p.y);
        acc.x = fmaf(av, v01.x, acc.x);
        acc.y = fmaf(av, v01.y, acc.y);
        acc.z = fmaf(av, v23.x, acc.z);
        acc.w = fmaf(av, v23.y, acc.w);
    }
    ((float4*)g_g)[(size_t)c * 32 + lane] = acc;
}

// ---------------------------------------------------------------------------
extern "C" void kernel_launch(void* const* d_in, const int* in_sizes, int n_in,
                              void* d_out, int out_size)
{
    const float* x      = (const float*)d_in[0];  // [N,128]
    const float* weight = (const float*)d_in[1];  // [128,128]
    const float* bias   = (const float*)d_in[2];  // [128]
    const float* wm     = (const float*)d_in[3];  // [256,128]
    const float* adj    = (const float*)d_in[4];  // [E]
    const int*   esrc   = (const int*)d_in[5];    // [E]
    float* out = (float*)d_out;

    void* pg;
    cudaGetSymbolAddress(&pg, g_g);

    cudaFuncSetAttribute(wm_gemm_k, cudaFuncAttributeMaxDynamicSharedMemorySize,
                         SM_TOTAL);
    cudaFuncSetAttribute(tc_gemm_k, cudaFuncAttributeMaxDynamicSharedMemorySize,
                         SM_TOTAL);

    const int gemm_grid = (NN + 127) / 128;  // 391
    const int warp_grid = (NN + 7) / 8;      // 6250

    // One-time weight conversion (3 matrices -> padded bf16 hi/lo images)
    wconv_k<<<3, 256>>>(wm, weight);

    // A = x@Wm_top (fp32) ; packed [B fp16 | x fp16] record
    wm_gemm_k<<<dim3(gemm_grid, 2), 256, SM_TOTAL>>>(x, NN);

    // x_new (fp16) = x + sum_e sigmoid(A[c]+B[s]) * x[s]
    edge_agg_k<<<warp_grid, 256>>>(x, esrc);

    // g[c] = sum_e adj[e] * x_new[s]
    gather_k<<<warp_grid, 256>>>(adj, esrc);

    // out = g @ weight + bias
    tc_gemm_k<<<gemm_grid, 256, SM_TOTAL>>>((const float*)pg, bias, out, NN);
}

// round 13
// speedup vs baseline: 1.2952x; 1.2754x over previous
#include <cuda_runtime.h>
#include <cuda_bf16.h>
#include <cuda_fp16.h>
#include <cstdint>

#define NN 50000
#define DEG 16

#define TSTRIDE 136
#define TBYTES (128 * TSTRIDE * 2)   // one 128x128 padded bf16 tile = 34816 B
#define WM_SMEM (6 * TBYTES)         // Ahi|Alo|B0hi|B0lo|B1hi|B1lo = 208896 B
#define TC_SMEM (4 * TBYTES)         // Ahi|Alo|Bhi|Blo = 139264 B

// Scratch
__device__ float g_A[(size_t)NN * 128];    // x @ Wm_top (fp32)
__device__ uint4 g_bx[(size_t)NN * 32];    // packed per node: [B fp16 x4 | x fp16 x4]
__device__ uint2 g_xnh[(size_t)NN * 32];   // x_new fp16
__device__ float g_g[(size_t)NN * 128];    // segment_sum(adj * x_new[src])

// ───────────────── tensor-core helpers (sm_80 baseline PTX) ─────────────────
__device__ __forceinline__ uint32_t smem_u32(const void* p) {
    uint32_t a;
    asm("{ .reg .u64 t; cvta.to.shared.u64 t, %1; cvt.u32.u64 %0, t; }"
        : "=r"(a) : "l"(p));
    return a;
}
__device__ __forceinline__ void ldsm_x4(uint32_t& r0, uint32_t& r1,
                                        uint32_t& r2, uint32_t& r3,
                                        uint32_t addr) {
    asm volatile("ldmatrix.sync.aligned.m8n8.x4.shared.b16 {%0,%1,%2,%3}, [%4];"
                 : "=r"(r0), "=r"(r1), "=r"(r2), "=r"(r3) : "r"(addr));
}
__device__ __forceinline__ void mma_bf16(float* c, const uint32_t* a,
                                         const uint32_t* b) {
    asm volatile(
        "mma.sync.aligned.m16n8k16.row.col.f32.bf16.bf16.f32 "
        "{%0,%1,%2,%3}, {%4,%5,%6,%7}, {%8,%9}, {%0,%1,%2,%3};"
        : "+f"(c[0]), "+f"(c[1]), "+f"(c[2]), "+f"(c[3])
        : "r"(a[0]), "r"(a[1]), "r"(a[2]), "r"(a[3]), "r"(b[0]), "r"(b[1]));
}

// split-convert 2 floats -> packed bf16x2 hi + packed bf16x2 lo (RN, exact
// reconstruction of hi via bit ops; identical rounding to __float2bfloat16_rn)
__device__ __forceinline__ void cvt2(float vx, float vy, uint32_t& hi, uint32_t& lo) {
    uint32_t p;
    asm("cvt.rn.bf16x2.f32 %0, %1, %2;" : "=r"(p) : "f"(vy), "f"(vx));
    const float fx = __uint_as_float(p << 16);
    const float fy = __uint_as_float(p & 0xffff0000u);
    uint32_t q;
    asm("cvt.rn.bf16x2.f32 %0, %1, %2;" : "=r"(q) : "f"(vy - fy), "f"(vx - fx));
    hi = p; lo = q;
}

// ===========================================================================
// wm_merged_k: one CTA (512 thr, 16 warps) computes BOTH Wm halves for a
// 128-row tile: A-convert once, mma over N=256.
//   y-half 0 output -> g_A fp32 (+ pack x fp16 into g_bx)
//   y-half 1 output -> packed B fp16 into g_bx
// ===========================================================================
__global__ __launch_bounds__(512, 1) void wm_merged_k(
    const float* __restrict__ X, const float* __restrict__ wm, int M)
{
    extern __shared__ char sh[];
    __nv_bfloat16* Ahi = (__nv_bfloat16*)(sh);
    __nv_bfloat16* Alo = (__nv_bfloat16*)(sh + TBYTES);

    const int tid  = threadIdx.x;
    const int lane = tid & 31;
    const int wid  = tid >> 5;
    const int row0 = blockIdx.x * 128;

    if (tid < 256) {
        // A: thread t -> row t>>1, k-half (t&1)*64 (+ pack x fp16)
        const int r  = tid >> 1;
        const int kh = (tid & 1) * 64;
        const bool valid = (row0 + r) < M;
        const float4* Xr = (const float4*)(X + (size_t)(row0 + r) * 128 + kh);
#pragma unroll
        for (int kk = 0; kk < 64; kk += 4) {
            float4 v = valid ? Xr[kk >> 2] : make_float4(0.f, 0.f, 0.f, 0.f);
            uint32_t h01, l01, h23, l23;
            cvt2(v.x, v.y, h01, l01);
            cvt2(v.z, v.w, h23, l23);
            const int k = kh + kk;
            *(uint2*)&Ahi[r * TSTRIDE + k] = make_uint2(h01, h23);
            *(uint2*)&Alo[r * TSTRIDE + k] = make_uint2(l01, l23);
            if (valid) {
                __half2 x01 = __floats2half2_rn(v.x, v.y);
                __half2 x23 = __floats2half2_rn(v.z, v.w);
                *(uint2*)((char*)&g_bx[(size_t)(row0 + r) * 32 + (k >> 2)] + 8) =
                    make_uint2(*(uint32_t*)&x01, *(uint32_t*)&x23);
            }
        }
    } else {
        // W: thread t2 -> matrix m = t2>>7, column n = t2&127 (coalesced reads)
        const int t2 = tid - 256;
        const int m = t2 >> 7, n = t2 & 127;
        const float* src = wm + (size_t)m * 128 * 128;
        __nv_bfloat16* Bh = (__nv_bfloat16*)(sh + 2 * TBYTES + m * 2 * TBYTES);
        __nv_bfloat16* Bl = (__nv_bfloat16*)((char*)Bh + TBYTES);
#pragma unroll 4
        for (int k = 0; k < 128; k += 4) {
            const float v0 = src[(k + 0) * 128 + n], v1 = src[(k + 1) * 128 + n];
            const float v2 = src[(k + 2) * 128 + n], v3 = src[(k + 3) * 128 + n];
            uint32_t h01, l01, h23, l23;
            cvt2(v0, v1, h01, l01);
            cvt2(v2, v3, h23, l23);
            *(uint2*)&Bh[n * TSTRIDE + k] = make_uint2(h01, h23);
            *(uint2*)&Bl[n * TSTRIDE + k] = make_uint2(l01, l23);
        }
    }
    __syncthreads();

    // ---- mainloop: 16 warps, warp tile 32(M) x 64(N) over 128x256 ----
    const int mr  = (wid & 3) * 32;
    const int nc  = (wid >> 2) * 64;     // 0..192
    const int m   = nc >> 7;             // output matrix
    const int ncl = nc & 127;

    float acc[2][8][4];
#pragma unroll
    for (int tm = 0; tm < 2; tm++)
#pragma unroll
        for (int j = 0; j < 8; j++)
#pragma unroll
            for (int q = 0; q < 4; q++) acc[tm][j][q] = 0.f;

    const uint32_t sb = smem_u32(sh);
    const uint32_t a_lane = ((lane & 15) * TSTRIDE + (lane >> 4) * 8) * 2;
    const uint32_t sA[2] = { sb + (uint32_t)(mr * TSTRIDE * 2) + a_lane,
                             sb + (uint32_t)((mr + 16) * TSTRIDE * 2) + a_lane };
    const uint32_t bbase = sb + 2 * TBYTES + (uint32_t)(m * 2 * TBYTES);
    const uint32_t sB[4] = { bbase + (uint32_t)(ncl * TSTRIDE * 2) + a_lane,
                             bbase + (uint32_t)((ncl + 16) * TSTRIDE * 2) + a_lane,
                             bbase + (uint32_t)((ncl + 32) * TSTRIDE * 2) + a_lane,
                             bbase + (uint32_t)((ncl + 48) * TSTRIDE * 2) + a_lane };

    const uint32_t aoff[3] = { 0u, 0u, (uint32_t)TBYTES };
    const uint32_t boff[3] = { 0u, (uint32_t)TBYTES, 0u };

#pragma unroll 1
    for (int p = 0; p < 3; p++) {
#pragma unroll
        for (int kk = 0; kk < 8; kk++) {
            const uint32_t kb = kk * 32;
            uint32_t a[2][4];
            ldsm_x4(a[0][0], a[0][1], a[0][2], a[0][3], sA[0] + aoff[p] + kb);
            ldsm_x4(a[1][0], a[1][1], a[1][2], a[1][3], sA[1] + aoff[p] + kb);
            uint32_t b[8][2];
#pragma unroll
            for (int jp = 0; jp < 4; jp++) {
                uint32_t m0, m1, m2, m3;
                ldsm_x4(m0, m1, m2, m3, sB[jp] + boff[p] + kb);
                b[2 * jp][0] = m0; b[2 * jp][1] = m2;
                b[2 * jp + 1][0] = m1; b[2 * jp + 1][1] = m3;
            }
#pragma unroll
            for (int tm = 0; tm < 2; tm++)
#pragma unroll
                for (int j = 0; j < 8; j++)
                    mma_bf16(acc[tm][j], a[tm], b[j]);
        }
    }

    // ---- epilogue ----
#pragma unroll
    for (int j = 0; j < 8; j++) {
        const int col = ncl + j * 8 + (lane & 3) * 2;
#pragma unroll
        for (int tm = 0; tm < 2; tm++) {
            const int ra = row0 + mr + tm * 16 + (lane >> 2);
            const int rb = ra + 8;
            if (m == 0) {
                if (ra < M)
                    *(float2*)(g_A + (size_t)ra * 128 + col) =
                        make_float2(acc[tm][j][0], acc[tm][j][1]);
                if (rb < M)
                    *(float2*)(g_A + (size_t)rb * 128 + col) =
                        make_float2(acc[tm][j][2], acc[tm][j][3]);
            } else {
                const uint32_t off = (uint32_t)((col >> 2) * 16 + (col & 3) * 2);
                if (ra < M) {
                    __half2 h = __floats2half2_rn(acc[tm][j][0], acc[tm][j][1]);
                    *(uint32_t*)((char*)&g_bx[(size_t)ra * 32] + off) = *(uint32_t*)&h;
                }
                if (rb < M) {
                    __half2 h = __floats2half2_rn(acc[tm][j][2], acc[tm][j][3]);
                    *(uint32_t*)((char*)&g_bx[(size_t)rb * 32] + off) = *(uint32_t*)&h;
                }
            }
        }
    }
}

// ===========================================================================
// tc_gemm_k (R8-proven structure): out = g_g @ weight + bias.
// 256 thr: tid<128 convert A rows, tid>=128 convert W columns (coalesced).
// ===========================================================================
__global__ __launch_bounds__(256) void tc_gemm_k(
    const float* __restrict__ X, const float* __restrict__ W,
    const float* __restrict__ bias, float* __restrict__ C, int M)
{
    extern __shared__ char sh[];
    __nv_bfloat16* Ahi = (__nv_bfloat16*)(sh);
    __nv_bfloat16* Alo = (__nv_bfloat16*)(sh + TBYTES);
    __nv_bfloat16* Bhi = (__nv_bfloat16*)(sh + 2 * TBYTES);
    __nv_bfloat16* Blo = (__nv_bfloat16*)(sh + 3 * TBYTES);

    const int tid  = threadIdx.x;
    const int lane = tid & 31;
    const int wid  = tid >> 5;
    const int row0 = blockIdx.x * 128;

    if (tid < 128) {
        const int r = tid;
        const bool valid = (row0 + r) < M;
        const float4* Xr = (const float4*)(X + (size_t)(row0 + r) * 128);
#pragma unroll 8
        for (int k = 0; k < 128; k += 4) {
            float4 v = valid ? Xr[k >> 2] : make_float4(0.f, 0.f, 0.f, 0.f);
            uint32_t h01, l01, h23, l23;
            cvt2(v.x, v.y, h01, l01);
            cvt2(v.z, v.w, h23, l23);
            *(uint2*)&Ahi[r * TSTRIDE + k] = make_uint2(h01, h23);
            *(uint2*)&Alo[r * TSTRIDE + k] = make_uint2(l01, l23);
        }
    } else {
        const int n = tid - 128;
#pragma unroll 4
        for (int k = 0; k < 128; k += 4) {
            const float v0 = W[(k + 0) * 128 + n], v1 = W[(k + 1) * 128 + n];
            const float v2 = W[(k + 2) * 128 + n], v3 = W[(k + 3) * 128 + n];
            uint32_t h01, l01, h23, l23;
            cvt2(v0, v1, h01, l01);
            cvt2(v2, v3, h23, l23);
            *(uint2*)&Bhi[n * TSTRIDE + k] = make_uint2(h01, h23);
            *(uint2*)&Blo[n * TSTRIDE + k] = make_uint2(l01, l23);
        }
    }
    __syncthreads();

    const int mr = (wid & 3) * 32;
    const int nc = (wid >> 2) * 64;

    float acc[2][8][4];
#pragma unroll
    for (int tm = 0; tm < 2; tm++)
#pragma unroll
        for (int j = 0; j < 8; j++)
#pragma unroll
            for (int q = 0; q < 4; q++) acc[tm][j][q] = 0.f;

    const uint32_t sb = smem_u32(sh);
    const uint32_t a_lane = ((lane & 15) * TSTRIDE + (lane >> 4) * 8) * 2;
    const uint32_t sA[2] = { sb + (uint32_t)(mr * TSTRIDE * 2) + a_lane,
                             sb + (uint32_t)((mr + 16) * TSTRIDE * 2) + a_lane };
    const uint32_t bbase = sb + 2 * TBYTES;
    const uint32_t sB[4] = { bbase + (uint32_t)(nc * TSTRIDE * 2) + a_lane,
                             bbase + (uint32_t)((nc + 16) * TSTRIDE * 2) + a_lane,
                             bbase + (uint32_t)((nc + 32) * TSTRIDE * 2) + a_lane,
                             bbase + (uint32_t)((nc + 48) * TSTRIDE * 2) + a_lane };

    const uint32_t aoff[3] = { 0u, 0u, (uint32_t)TBYTES };
    const uint32_t boff[3] = { 0u, (uint32_t)TBYTES, 0u };

#pragma unroll 1
    for (int p = 0; p < 3; p++) {
#pragma unroll
        for (int kk = 0; kk < 8; kk++) {
            const uint32_t kb = kk * 32;
            uint32_t a[2][4];
            ldsm_x4(a[0][0], a[0][1], a[0][2], a[0][3], sA[0] + aoff[p] + kb);
            ldsm_x4(a[1][0], a[1][1], a[1][2], a[1][3], sA[1] + aoff[p] + kb);
            uint32_t b[8][2];
#pragma unroll
            for (int jp = 0; jp < 4; jp++) {
                uint32_t m0, m1, m2, m3;
                ldsm_x4(m0, m1, m2, m3, sB[jp] + boff[p] + kb);
                b[2 * jp][0] = m0; b[2 * jp][1] = m2;
                b[2 * jp + 1][0] = m1; b[2 * jp + 1][1] = m3;
            }
#pragma unroll
            for (int tm = 0; tm < 2; tm++)
#pragma unroll
                for (int j = 0; j < 8; j++)
                    mma_bf16(acc[tm][j], a[tm], b[j]);
        }
    }

#pragma unroll
    for (int j = 0; j < 8; j++) {
        const int col = nc + j * 8 + (lane & 3) * 2;
        const float2 bv = *(const float2*)(bias + col);
#pragma unroll
        for (int tm = 0; tm < 2; tm++) {
            const int ra = row0 + mr + tm * 16 + (lane >> 2);
            const int rb = ra + 8;
            if (ra < M)
                *(float2*)(C + (size_t)ra * 128 + col) =
                    make_float2(acc[tm][j][0] + bv.x, acc[tm][j][1] + bv.y);
            if (rb < M)
                *(float2*)(C + (size_t)rb * 128 + col) =
                    make_float2(acc[tm][j][2] + bv.x, acc[tm][j][3] + bv.y);
        }
    }
}

__device__ __forceinline__ float sig_t(float half_arg) {
    // sigmoid(2*half_arg) = 0.5*tanh(half_arg) + 0.5
    float t;
    asm("tanh.approx.f32 %0, %1;" : "=f"(t) : "f"(half_arg));
    return fmaf(0.5f, t, 0.5f);
}

// ---------------------------------------------------------------------------
// Warp per node: x_new[c] = x[c] + sum_e sigmoid(A[c]+B[s]) * x[s]
// ---------------------------------------------------------------------------
__global__ __launch_bounds__(256) void edge_agg_k(
    const float* __restrict__ x, const int* __restrict__ esrc)
{
    const int gw   = (blockIdx.x * 256 + threadIdx.x) >> 5;
    const int lane = threadIdx.x & 31;
    if (gw >= NN) return;
    const int c    = gw;
    const int s_my = esrc[c * DEG + (lane & 15)];

    const float4 a = ((const float4*)g_A)[(size_t)c * 32 + lane];
    const __half2 h05  = __floats2half2_rn(0.5f, 0.5f);
    const __half2 ha01 = __floats2half2_rn(0.5f * a.x, 0.5f * a.y);
    const __half2 ha23 = __floats2half2_rn(0.5f * a.z, 0.5f * a.w);

    float4 acc = make_float4(0.f, 0.f, 0.f, 0.f);

#pragma unroll
    for (int e = 0; e < DEG; e++) {
        const int   s = __shfl_sync(0xffffffffu, s_my, e);
        const uint4 p = g_bx[(size_t)s * 32 + lane];
        const __half2 b01 = *(const __half2*)&p.x;
        const __half2 b23 = *(const __half2*)&p.y;
        const float2 h01 = __half22float2(__hfma2(b01, h05, ha01));
        const float2 h23 = __half22float2(__hfma2(b23, h05, ha23));
        const float2 xf01 = __half22float2(*(const __half2*)&p.z);
        const float2 xf23 = __half22float2(*(const __half2*)&p.w);
        acc.x = fmaf(sig_t(h01.x), xf01.x, acc.x);
        acc.y = fmaf(sig_t(h01.y), xf01.y, acc.y);
        acc.z = fmaf(sig_t(h23.x), xf23.x, acc.z);
        acc.w = fmaf(sig_t(h23.y), xf23.y, acc.w);
    }

    const float4 xc = ((const float4*)x)[(size_t)c * 32 + lane];
    __half2 o01 = __floats2half2_rn(xc.x + acc.x, xc.y + acc.y);
    __half2 o23 = __floats2half2_rn(xc.z + acc.z, xc.w + acc.w);
    g_xnh[(size_t)c * 32 + lane] = make_uint2(*(uint32_t*)&o01, *(uint32_t*)&o23);
}

// ---------------------------------------------------------------------------
// Warp per node: g[c] = sum_e adj[e] * x_new_fp16[s_e]  (fp32 out)
// ---------------------------------------------------------------------------
__global__ __launch_bounds__(256) void gather_k(
    const float* __restrict__ adj, const int* __restrict__ esrc)
{
    const int gw   = (blockIdx.x * 256 + threadIdx.x) >> 5;
    const int lane = threadIdx.x & 31;
    if (gw >= NN) return;
    const int   c    = gw;
    const int   s_my = esrc[c * DEG + (lane & 15)];
    const float a_my = adj[c * DEG + (lane & 15)];

    float4 acc = make_float4(0.f, 0.f, 0.f, 0.f);

#pragma unroll
    for (int e = 0; e < DEG; e++) {
        const int   s  = __shfl_sync(0xffffffffu, s_my, e);
        const float av = __shfl_sync(0xffffffffu, a_my, e);
        const uint2 p  = g_xnh[(size_t)s * 32 + lane];
        const float2 v01 = __half22float2(*(const __half2*)&p.x);
        const float2 v23 = __half22float2(*(const __half2*)&p.y);
        acc.x = fmaf(av, v01.x, acc.x);
        acc.y = fmaf(av, v01.y, acc.y);
        acc.z = fmaf(av, v23.x, acc.z);
        acc.w = fmaf(av, v23.y, acc.w);
    }
    ((float4*)g_g)[(size_t)c * 32 + lane] = acc;
}

// ---------------------------------------------------------------------------
extern "C" void kernel_launch(void* const* d_in, const int* in_sizes, int n_in,
                              void* d_out, int out_size)
{
    const float* x      = (const float*)d_in[0];  // [N,128]
    const float* weight = (const float*)d_in[1];  // [128,128]
    const float* bias   = (const float*)d_in[2];  // [128]
    const float* wm     = (const float*)d_in[3];  // [256,128]
    const float* adj    = (const float*)d_in[4];  // [E]
    const int*   esrc   = (const int*)d_in[5];    // [E]
    float* out = (float*)d_out;

    void* pg;
    cudaGetSymbolAddress(&pg, g_g);

    cudaFuncSetAttribute(wm_merged_k, cudaFuncAttributeMaxDynamicSharedMemorySize,
                         WM_SMEM);
    cudaFuncSetAttribute(tc_gemm_k, cudaFuncAttributeMaxDynamicSharedMemorySize,
                         TC_SMEM);

    const int gemm_grid = (NN + 127) / 128;  // 391
    const int warp_grid = (NN + 7) / 8;      // 6250

    // A = x@Wm_top (fp32) and B = x@Wm_bot (fp16, packed) in one launch
    wm_merged_k<<<gemm_grid, 512, WM_SMEM>>>(x, wm, NN);

    // x_new (fp16) = x + sum_e sigmoid(A[c]+B[s]) * x[s]
    edge_agg_k<<<warp_grid, 256>>>(x, esrc);

    // g[c] = sum_e adj[e] * x_new[s]
    gather_k<<<warp_grid, 256>>>(adj, esrc);

    // out = g @ weight + bias
    tc_gemm_k<<<gemm_grid, 256, TC_SMEM>>>((const float*)pg, weight, bias, out, NN);
}